// round 14
// baseline (speedup 1.0000x reference)
#include <cuda_runtime.h>
#include <cuda_bf16.h>
#include <cstdint>

#define EPSF 1e-6f
#define TWO_PI_F 6.283185307179586f
#define NB_BASE 32
#define TPB 256
#define CHUNK 1024          // points per chunk (fast path, M=2048)
#define NC 2                // chunks per event
#define EPB 2               // events per block (fast path)

__device__ __forceinline__ uint32_t smem_u32(const void* p) {
    uint32_t a;
    asm("{ .reg .u64 tmp; cvta.to.shared.u64 tmp, %1; cvt.u32.u64 %0, tmp; }"
        : "=r"(a) : "l"(p));
    return a;
}
__device__ __forceinline__ void bulk_g2s(uint32_t smem_addr, const void* gptr,
                                         uint32_t bytes, uint32_t mbar_addr) {
    asm volatile(
        "cp.async.bulk.shared::cta.global.mbarrier::complete_tx::bytes "
        "[%0], [%1], %2, [%3];"
        :: "r"(smem_addr), "l"(gptr), "r"(bytes), "r"(mbar_addr) : "memory");
}
__device__ __forceinline__ void mbar_init(uint32_t mbar, uint32_t cnt) {
    asm volatile("mbarrier.init.shared.b64 [%0], %1;" :: "r"(mbar), "r"(cnt) : "memory");
}
__device__ __forceinline__ void mbar_expect_tx(uint32_t mbar, uint32_t bytes) {
    asm volatile("mbarrier.arrive.expect_tx.shared.b64 _, [%0], %1;"
                 :: "r"(mbar), "r"(bytes) : "memory");
}
__device__ __forceinline__ void mbar_wait(uint32_t mbar, uint32_t parity) {
    asm volatile(
        "{\n\t"
        ".reg .pred P1;\n\t"
        "WAIT_LOOP_%=:\n\t"
        "mbarrier.try_wait.parity.acquire.cta.shared::cta.b64 P1, [%0], %1, 0x989680;\n\t"
        "@P1 bra.uni WAIT_DONE_%=;\n\t"
        "bra.uni WAIT_LOOP_%=;\n\t"
        "WAIT_DONE_%=:\n\t"
        "}"
        :: "r"(mbar), "r"(parity) : "memory");
}

// ---------------------------------------------------------------------------
// Fused kernel.
//   blocks [0, NB_BASE)        : base-rate grid partials -> atomicAdd out[N]
//   blocks [NB_BASE, ...)      : EPB events per block, chunked double-buffer
//                                cp.async.bulk pipeline.
// out[N] zeroed by a memset node before this kernel.
// ---------------------------------------------------------------------------
__global__ __launch_bounds__(TPB) void k_fused(
    const float* __restrict__ x, const float* __restrict__ t,
    const float* __restrict__ past_x, const float* __restrict__ past_t,
    const float* __restrict__ cov,
    const float* __restrict__ z, const float* __restrict__ x_grid,
    const float* __restrict__ t_grid, const float* __restrict__ beta,
    const float* __restrict__ p_alpha, const float* __restrict__ p_sigma,
    const float* __restrict__ p_omega,
    int N, int M, int G, int T, int D, int rows, int fast,
    float* __restrict__ out)
{
    __shared__ __align__(16) float sm_t[2][CHUNK];       // 2 x 4 KB
    __shared__ __align__(16) float sm_x[2][2 * CHUNK];   // 2 x 8 KB
    __shared__ __align__(8)  uint64_t sm_mbar[2];
    __shared__ float smS[8], smA[8], smB[8];
    __shared__ float sm_mu;

    const int tid  = threadIdx.x;
    const int warp = tid >> 5;
    const int lane = tid & 31;

    const float alpha = *p_alpha;
    const float sigma = *p_sigma;
    const float omega = *p_omega;
    const float inv2s2 = 1.0f / (2.0f * sigma * sigma);
    const float Cf     = alpha * omega / (TWO_PI_F * sigma * sigma);
    const float dt_step = t_grid[1] - t_grid[0];
    const float scale   = dt_step / (float)G;    // dxdy * dt_step

    if (blockIdx.x < (unsigned)NB_BASE) {
        // ================= base-rate partial blocks =================
        const int bj = blockIdx.x;
        float bta[16];
        #pragma unroll
        for (int d = 0; d < 16; d++) bta[d] = (d < D) ? beta[d] : 0.0f;

        float s = 0.0f;
        if (D == 16) {
            for (int r = bj * TPB + tid; r < rows; r += NB_BASE * TPB) {
                const float4* __restrict__ zr =
                    reinterpret_cast<const float4*>(z + (size_t)r * 16);
                float4 v0 = zr[0], v1 = zr[1], v2 = zr[2], v3 = zr[3];
                float dot = 0.0f;
                dot = fmaf(v0.x, bta[0],  dot); dot = fmaf(v0.y, bta[1],  dot);
                dot = fmaf(v0.z, bta[2],  dot); dot = fmaf(v0.w, bta[3],  dot);
                dot = fmaf(v1.x, bta[4],  dot); dot = fmaf(v1.y, bta[5],  dot);
                dot = fmaf(v1.z, bta[6],  dot); dot = fmaf(v1.w, bta[7],  dot);
                dot = fmaf(v2.x, bta[8],  dot); dot = fmaf(v2.y, bta[9],  dot);
                dot = fmaf(v2.z, bta[10], dot); dot = fmaf(v2.w, bta[11], dot);
                dot = fmaf(v3.x, bta[12], dot); dot = fmaf(v3.y, bta[13], dot);
                dot = fmaf(v3.z, bta[14], dot); dot = fmaf(v3.w, bta[15], dot);
                s += fmaxf(dot, EPSF);
            }
        } else {
            for (int r = bj * TPB + tid; r < rows; r += NB_BASE * TPB) {
                float dot = 0.0f;
                for (int d = 0; d < D; d++)
                    dot = fmaf(z[(size_t)r * D + d], beta[d], dot);
                s += fmaxf(dot, EPSF);
            }
        }
        #pragma unroll
        for (int o = 16; o > 0; o >>= 1)
            s += __shfl_down_sync(0xffffffffu, s, o);
        if (lane == 0) smS[warp] = s;
        __syncthreads();
        if (tid == 0) {
            float S = 0.0f;
            #pragma unroll
            for (int w = 0; w < 8; w++) S += smS[w];
            atomicAdd(out + N, S * scale);
        }
        return;
    }

    const float2* __restrict__ gx = reinterpret_cast<const float2*>(x_grid);

    if (fast) {
        // ============ pipelined event blocks: EPB events, NC chunks each ====
        const int base = (blockIdx.x - NB_BASE) * EPB;
        const int cnt  = (N - base < EPB) ? (N - base) : EPB;
        if (cnt <= 0) return;
        const int TOTC = cnt * NC;

        const uint32_t mb0 = smem_u32(&sm_mbar[0]);
        const uint32_t mb1 = smem_u32(&sm_mbar[1]);

        if (tid == 0) { mbar_init(mb0, 1); mbar_init(mb1, 1); }
        __syncthreads();

        // prologue: issue chunk 0 (and 1) loads
        if (tid == 0) {
            #pragma unroll
            for (int j = 0; j < 2; j++) {
                if (j < TOTC) {
                    const int ei = base + j / NC;
                    const int c  = j % NC;
                    const uint32_t mbj = j ? mb1 : mb0;
                    mbar_expect_tx(mbj, CHUNK * 12u);
                    bulk_g2s(smem_u32(sm_t[j]),
                             past_t + (size_t)ei * M + c * CHUNK,
                             CHUNK * 4u, mbj);
                    bulk_g2s(smem_u32(sm_x[j]),
                             past_x + (size_t)ei * 2 * M + c * 2 * CHUNK,
                             CHUNK * 8u, mbj);
                }
            }
        }

        float s = 0.0f, a = 0.0f, bfac = 0.0f, mu = 0.0f;
        float xi = 0.0f, yi = 0.0f, ti = 0.0f;

        for (int j = 0; j < TOTC; j++) {
            const int ei = base + j / NC;

            if ((j % NC) == 0) {
                // new event: overlap A/B/mu compute with in-flight copy
                xi = x[2 * ei]; yi = x[2 * ei + 1]; ti = t[ei];
                s = 0.0f; a = 0.0f; bfac = 0.0f; mu = 0.0f;

                for (int g = tid; g < G; g += TPB) {
                    float2 p  = gx[g];
                    float  dx = p.x - xi;
                    float  dy = p.y - yi;
                    a += __expf(-(dx * dx + dy * dy) * inv2s2);
                }
                for (int k = tid; k < T; k += TPB) {
                    float dtau = t_grid[k] - ti;
                    if (dtau > 0.0f) bfac += __expf(-omega * dtau);
                }
                if (tid < D) mu = cov[(size_t)ei * D + tid] * beta[tid];
            }

            const int b = j & 1;
            mbar_wait(b ? mb1 : mb0, (j >> 1) & 1);

            {
                const float4* __restrict__ st4 =
                    reinterpret_cast<const float4*>(sm_t[b]);
                const float4* __restrict__ sx4 =
                    reinterpret_cast<const float4*>(sm_x[b]);
                float4 tt = st4[tid];
                float4 p0 = sx4[2 * tid];
                float4 p1 = sx4[2 * tid + 1];
                float dt, dx, dy, r2, e;
                dt = ti - tt.x; dx = xi - p0.x; dy = yi - p0.y; r2 = dx*dx + dy*dy;
                e = __expf(-(r2 * inv2s2 + omega * dt)); s += (dt > 0.0f) ? e : 0.0f;
                dt = ti - tt.y; dx = xi - p0.z; dy = yi - p0.w; r2 = dx*dx + dy*dy;
                e = __expf(-(r2 * inv2s2 + omega * dt)); s += (dt > 0.0f) ? e : 0.0f;
                dt = ti - tt.z; dx = xi - p1.x; dy = yi - p1.y; r2 = dx*dx + dy*dy;
                e = __expf(-(r2 * inv2s2 + omega * dt)); s += (dt > 0.0f) ? e : 0.0f;
                dt = ti - tt.w; dx = xi - p1.z; dy = yi - p1.w; r2 = dx*dx + dy*dy;
                e = __expf(-(r2 * inv2s2 + omega * dt)); s += (dt > 0.0f) ? e : 0.0f;
            }
            __syncthreads();   // all threads done consuming buffer b

            if (tid == 0 && j + 2 < TOTC) {
                const int jn = j + 2;
                const int en = base + jn / NC;
                const int c  = jn % NC;
                const uint32_t mbj = b ? mb1 : mb0;
                mbar_expect_tx(mbj, CHUNK * 12u);
                bulk_g2s(smem_u32(sm_t[b]),
                         past_t + (size_t)en * M + c * CHUNK,
                         CHUNK * 4u, mbj);
                bulk_g2s(smem_u32(sm_x[b]),
                         past_x + (size_t)en * 2 * M + c * 2 * CHUNK,
                         CHUNK * 8u, mbj);
            }

            if ((j % NC) == NC - 1) {
                // ---- emit event ei ----
                float sv = s, av = a, bv = bfac, mv = mu;
                #pragma unroll
                for (int o = 16; o > 0; o >>= 1) {
                    sv += __shfl_down_sync(0xffffffffu, sv, o);
                    av += __shfl_down_sync(0xffffffffu, av, o);
                    bv += __shfl_down_sync(0xffffffffu, bv, o);
                    mv += __shfl_down_sync(0xffffffffu, mv, o);
                }
                if (lane == 0) { smS[warp] = sv; smA[warp] = av; smB[warp] = bv; }
                if (tid == 0) sm_mu = mv;
                __syncthreads();
                if (tid == 0) {
                    float S = 0.0f, A = 0.0f, B = 0.0f;
                    #pragma unroll
                    for (int w = 0; w < 8; w++) { S += smS[w]; A += smA[w]; B += smB[w]; }
                    float m = fmaxf(sm_mu, EPSF);
                    out[ei] = logf(m + Cf * S + EPSF);
                    atomicAdd(out + N, Cf * A * B * scale);
                }
                __syncthreads();   // protect smS/A/B before next event
            }
        }
    } else {
        // ============ generic fallback: one event per block, direct LDG =====
        const int i = blockIdx.x - NB_BASE;
        if (i >= N) return;

        const float xi = x[2 * i];
        const float yi = x[2 * i + 1];
        const float ti = t[i];

        const float4* __restrict__ pt4 =
            reinterpret_cast<const float4*>(past_t + (size_t)i * M);
        const float4* __restrict__ px4 =
            reinterpret_cast<const float4*>(past_x + (size_t)i * 2 * M);

        float s = 0.0f;
        for (int sl = tid; sl < M / 4; sl += TPB) {
            float4 tt = pt4[sl];
            float4 p0 = px4[2 * sl];
            float4 p1 = px4[2 * sl + 1];
            float dt, dx, dy, r2, e;
            dt = ti - tt.x; dx = xi - p0.x; dy = yi - p0.y; r2 = dx*dx + dy*dy;
            e = __expf(-(r2 * inv2s2 + omega * dt)); s += (dt > 0.0f) ? e : 0.0f;
            dt = ti - tt.y; dx = xi - p0.z; dy = yi - p0.w; r2 = dx*dx + dy*dy;
            e = __expf(-(r2 * inv2s2 + omega * dt)); s += (dt > 0.0f) ? e : 0.0f;
            dt = ti - tt.z; dx = xi - p1.x; dy = yi - p1.y; r2 = dx*dx + dy*dy;
            e = __expf(-(r2 * inv2s2 + omega * dt)); s += (dt > 0.0f) ? e : 0.0f;
            dt = ti - tt.w; dx = xi - p1.z; dy = yi - p1.w; r2 = dx*dx + dy*dy;
            e = __expf(-(r2 * inv2s2 + omega * dt)); s += (dt > 0.0f) ? e : 0.0f;
        }

        float a = 0.0f;
        for (int g = tid; g < G; g += TPB) {
            float2 p  = gx[g];
            float  dx = p.x - xi;
            float  dy = p.y - yi;
            a += __expf(-(dx * dx + dy * dy) * inv2s2);
        }
        float bfac = 0.0f;
        for (int k = tid; k < T; k += TPB) {
            float dtau = t_grid[k] - ti;
            if (dtau > 0.0f) bfac += __expf(-omega * dtau);
        }
        float mu = 0.0f;
        if (tid < D) mu = cov[(size_t)i * D + tid] * beta[tid];

        #pragma unroll
        for (int o = 16; o > 0; o >>= 1) {
            s    += __shfl_down_sync(0xffffffffu, s,    o);
            a    += __shfl_down_sync(0xffffffffu, a,    o);
            bfac += __shfl_down_sync(0xffffffffu, bfac, o);
            mu   += __shfl_down_sync(0xffffffffu, mu,   o);
        }
        if (lane == 0) { smS[warp] = s; smA[warp] = a; smB[warp] = bfac; }
        if (tid == 0) sm_mu = mu;
        __syncthreads();
        if (tid == 0) {
            float S = 0.0f, A = 0.0f, B = 0.0f;
            #pragma unroll
            for (int w = 0; w < 8; w++) { S += smS[w]; A += smA[w]; B += smB[w]; }
            float m = fmaxf(sm_mu, EPSF);
            out[i] = logf(m + Cf * S + EPSF);
            atomicAdd(out + N, Cf * A * B * scale);
        }
    }
}

// ---------------------------------------------------------------------------
extern "C" void kernel_launch(void* const* d_in, const int* in_sizes, int n_in,
                              void* d_out, int out_size)
{
    const float* x       = (const float*)d_in[0];
    const float* t       = (const float*)d_in[1];
    const float* past_x  = (const float*)d_in[2];
    const float* past_t  = (const float*)d_in[3];
    const float* cov     = (const float*)d_in[4];
    const float* z_grid  = (const float*)d_in[5];
    const float* x_grid  = (const float*)d_in[6];
    const float* t_grid  = (const float*)d_in[7];
    const float* beta    = (const float*)d_in[8];
    const float* p_alpha = (const float*)d_in[9];
    const float* p_sigma = (const float*)d_in[10];
    const float* p_omega = (const float*)d_in[11];
    float* out = (float*)d_out;

    const int N = in_sizes[1];
    const int M = in_sizes[3] / N;
    const int D = in_sizes[8];
    const int G = in_sizes[6] / 2;
    const int T = in_sizes[7];
    const int rows = in_sizes[5] / D;   // T*G

    const int fast = (M == 2 * CHUNK) ? 1 : 0;
    const int nev_blocks = fast ? (N + EPB - 1) / EPB : N;

    cudaMemsetAsync(out + N, 0, sizeof(float));

    k_fused<<<NB_BASE + nev_blocks, TPB>>>(
        x, t, past_x, past_t, cov, z_grid, x_grid, t_grid, beta,
        p_alpha, p_sigma, p_omega, N, M, G, T, D, rows, fast, out);
}